// round 5
// baseline (speedup 1.0000x reference)
#include <cuda_runtime.h>
#include <cuda_bf16.h>

// Problem constants (pinned by the reference)
#define B_DIM   64
#define S_DIM   8192
#define D_DIM   64
#define N_BINS  256            // output bins; bin 256 = dummy (T >= 256)
#define STARTS_PER_B (N_BINS + 2)   // 258: exclusive prefix for bins 0..256, plus total

// Scratch (allocation-free rule: __device__ globals)
__device__ int g_sorted_x[B_DIM * S_DIM];          // token ids, bin-contiguous per batch
__device__ int g_start[B_DIM * STARTS_PER_B];      // per-batch exclusive bin offsets

// ---------------------------------------------------------------------------
// K1: per-batch counting sort of token ids by time-bin.
// One CTA per batch (64 CTAs x 1024 threads).
//   pass 1: bin = (t < 256) ? floor(t) : 256 ; smem histogram (int atomics)
//   scan  : thread 0 exclusive prefix over 257 bins -> smem offs + g_start
//   pass 2: pos = atomicAdd(offs[bin]) ; g_sorted_x[b][pos] = X_ids[b][s]
// ---------------------------------------------------------------------------
__global__ __launch_bounds__(1024, 1)
void k_bin_sort(const float* __restrict__ T, const int* __restrict__ X)
{
    __shared__ int hist[N_BINS + 1];
    __shared__ int offs[N_BINS + 1];
    __shared__ unsigned short sbin[S_DIM];   // 16 KB: cache bins between passes

    const int b   = blockIdx.x;
    const int tid = threadIdx.x;

    for (int i = tid; i <= N_BINS; i += 1024) hist[i] = 0;
    __syncthreads();

    const float* Tb = T + b * S_DIM;
    #pragma unroll 2
    for (int s = tid; s < S_DIM; s += 1024) {
        float t  = Tb[s];
        int bin  = (t < 256.0f) ? (int)t : N_BINS;   // t >= 0, so (int)t == floor
        sbin[s]  = (unsigned short)bin;
        atomicAdd(&hist[bin], 1);
    }
    __syncthreads();

    if (tid == 0) {
        int run = 0;
        int* gs = g_start + b * STARTS_PER_B;
        #pragma unroll 1
        for (int i = 0; i <= N_BINS; ++i) {
            offs[i] = run;
            gs[i]   = run;
            run    += hist[i];
        }
        gs[N_BINS + 1] = run;   // == S_DIM
    }
    __syncthreads();

    const int* Xb  = X + b * S_DIM;
    int*       dst = g_sorted_x + b * S_DIM;
    #pragma unroll 2
    for (int s = tid; s < S_DIM; s += 1024) {
        int bin = sbin[s];
        int pos = atomicAdd(&offs[bin], 1);
        dst[pos] = Xb[s];
    }
}

// ---------------------------------------------------------------------------
// K2: one warp per (batch, bin). Lane l owns output dims {2l, 2l+1} (float2).
// Register accumulation over the bin's token list; no atomics anywhere.
//   x    : broadcast load (all lanes same address)
//   w    : __expf(embedW[x]) broadcast (1 sector per token)
//   emb  : float2 gather, warp reads one contiguous 256B row per token
// out[b][bin][:] = acc / (n + 1e-6)
// ---------------------------------------------------------------------------
__global__ __launch_bounds__(256, 8)
void k_bin_reduce(const float* __restrict__ embedX,
                  const float* __restrict__ embedW,
                  float* __restrict__ out)
{
    const int warp = (blockIdx.x * blockDim.x + threadIdx.x) >> 5;  // 0 .. 16383
    const int lane = threadIdx.x & 31;
    const int b    = warp >> 8;       // 0..63
    const int bin  = warp & 255;      // 0..255  (dummy bin 256 never processed)

    const int* gs = g_start + b * STARTS_PER_B;
    const int  s0 = gs[bin];
    const int  s1 = gs[bin + 1];

    const int*    sx = g_sorted_x + b * S_DIM;
    const float2* ex = reinterpret_cast<const float2*>(embedX);

    float2 acc = make_float2(0.0f, 0.0f);

    // Unroll: batches 4 independent token-id loads -> MLP for the gathers.
    #pragma unroll 4
    for (int i = s0; i < s1; ++i) {
        int    x = __ldg(&sx[i]);
        float  w = __expf(__ldg(&embedW[x]));
        float2 e = __ldg(&ex[x * 32 + lane]);
        acc.x = fmaf(w, e.x, acc.x);
        acc.y = fmaf(w, e.y, acc.y);
    }

    float inv = 1.0f / ((float)(s1 - s0) + 1e-6f);
    float2 r;
    r.x = acc.x * inv;
    r.y = acc.y * inv;
    reinterpret_cast<float2*>(out)[(b * N_BINS + bin) * 32 + lane] = r;
}

// ---------------------------------------------------------------------------
// Inputs (metadata order):
//   d_in[0] : T        float32 [B, S]
//   d_in[1] : X_ids    int32   [B, S]
//   d_in[2] : embedX_w float32 [N_TOKENS+1, 64]
//   d_in[3] : embedW_w float32 [N_TOKENS+1, 1]
// Output    : float32 [B, 256, 64]
// ---------------------------------------------------------------------------
extern "C" void kernel_launch(void* const* d_in, const int* in_sizes, int n_in,
                              void* d_out, int out_size)
{
    const float* T      = (const float*)d_in[0];
    const int*   X_ids  = (const int*)  d_in[1];
    const float* embedX = (const float*)d_in[2];
    const float* embedW = (const float*)d_in[3];
    float*       out    = (float*)d_out;

    k_bin_sort<<<B_DIM, 1024>>>(T, X_ids);

    // 64 batches * 256 bins = 16384 warps; 8 warps/CTA -> 2048 CTAs
    k_bin_reduce<<<(B_DIM * N_BINS) / 8, 256>>>(embedX, embedW, out);
}

// round 6
// speedup vs baseline: 1.1617x; 1.1617x over previous
#include <cuda_runtime.h>
#include <cuda_bf16.h>

// Problem constants (pinned by the reference)
#define B_DIM   64
#define S_DIM   8192
#define D_DIM   64
#define N_BINS  256                 // output bins; bin 256 = dummy (T >= 256)
#define NCHUNK  4                   // CTAs per batch in the sort phase
#define CHUNK_S (S_DIM / NCHUNK)    // 2048 tokens per chunk
#define NBIN1   (N_BINS + 1)        // 257 (incl. dummy)
#define STARTS_PER_B 258

// Scratch (allocation-free rule: __device__ globals)
__device__ int2           g_sorted[B_DIM * S_DIM];            // (x, w-bits), bin-contiguous per batch
__device__ unsigned short g_bins  [B_DIM * S_DIM];            // cached bin per token
__device__ int            g_hist  [B_DIM * NCHUNK * NBIN1];   // per-(batch,chunk) histograms
__device__ int            g_start [B_DIM * STARTS_PER_B];     // per-batch exclusive bin starts

// ---------------------------------------------------------------------------
// K1a: per-(batch,chunk) histogram. 256 CTAs x 512 threads.
// bin = (t < 256) ? floor(t) : 256. Caches bins in g_bins for the scatter pass.
// ---------------------------------------------------------------------------
__global__ __launch_bounds__(512, 2)
void k_hist(const float* __restrict__ T)
{
    __shared__ int hist[NBIN1];
    const int b   = blockIdx.x >> 2;
    const int c   = blockIdx.x & 3;
    const int tid = threadIdx.x;

    for (int i = tid; i < NBIN1; i += 512) hist[i] = 0;
    __syncthreads();

    const float*    Tb = T      + b * S_DIM + c * CHUNK_S;
    unsigned short* bb = g_bins + b * S_DIM + c * CHUNK_S;

    #pragma unroll 4
    for (int s = tid; s < CHUNK_S; s += 512) {
        float t  = Tb[s];
        int bin  = (t < 256.0f) ? (int)t : N_BINS;   // t >= 0 -> (int)t == floor
        bb[s]    = (unsigned short)bin;
        atomicAdd(&hist[bin], 1);
    }
    __syncthreads();

    int* gh = g_hist + (b * NCHUNK + c) * NBIN1;
    for (int i = tid; i < NBIN1; i += 512) gh[i] = hist[i];
}

// ---------------------------------------------------------------------------
// K1b: per-(batch,chunk) scan + scatter. 256 CTAs x 512 threads.
// Each CTA reconstructs the batch-wide exclusive bin bases (257-entry smem
// scan over the summed chunk histograms) plus its own chunk's running offset,
// then scatters packed (x, exp(embedW[x])) pairs with PRIVATE smem offsets
// (no cross-CTA atomics). Chunk-0 CTAs also publish g_start for K2.
// ---------------------------------------------------------------------------
__global__ __launch_bounds__(512, 2)
void k_scan_scatter(const int* __restrict__ X, const float* __restrict__ embedW)
{
    __shared__ int scan[NBIN1];
    __shared__ int offs[NBIN1];

    const int b   = blockIdx.x >> 2;
    const int c   = blockIdx.x & 3;
    const int tid = threadIdx.x;

    int tot = 0, part = 0;
    if (tid < NBIN1) {
        #pragma unroll
        for (int cc = 0; cc < NCHUNK; ++cc) {
            int h = g_hist[(b * NCHUNK + cc) * NBIN1 + tid];
            tot += h;
            if (cc < c) part += h;
        }
        scan[tid] = tot;
    }
    __syncthreads();

    // Hillis-Steele inclusive scan over 257 entries
    for (int d = 1; d < NBIN1; d <<= 1) {
        int v = 0;
        if (tid < NBIN1 && tid >= d) v = scan[tid - d];
        __syncthreads();
        if (tid < NBIN1) scan[tid] += v;
        __syncthreads();
    }

    if (tid < NBIN1) {
        int base = scan[tid] - tot;          // exclusive prefix = bin start
        offs[tid] = base + part;             // this chunk's write cursor
        if (c == 0) {
            g_start[b * STARTS_PER_B + tid] = base;
            if (tid == 0) g_start[b * STARTS_PER_B + NBIN1] = S_DIM;
        }
    }
    __syncthreads();

    const int*            Xb  = X      + b * S_DIM + c * CHUNK_S;
    const unsigned short* bb  = g_bins + b * S_DIM + c * CHUNK_S;
    int2*                 dst = g_sorted + b * S_DIM;

    #pragma unroll 4
    for (int s = tid; s < CHUNK_S; s += 512) {
        int   bin = bb[s];
        int   x   = Xb[s];
        float w   = __expf(__ldg(&embedW[x]));
        int   pos = atomicAdd(&offs[bin], 1);
        dst[pos]  = make_int2(x, __float_as_int(w));
    }
}

// ---------------------------------------------------------------------------
// K2: one warp per (batch, bin). Lane l owns output dims {2l, 2l+1}.
// A single coalesced 256B load fetches 32 (x,w) pairs; __shfl distributes
// them so every gather depends only on a 26-cyc shuffle, not an L2 round
// trip. Padded lanes carry x=0 (zero row) and w=0 -> contribute exactly 0,
// so the inner loop has a FIXED 32-iteration trip count and unrolls fully.
// ---------------------------------------------------------------------------
__global__ __launch_bounds__(256, 8)
void k_bin_reduce(const float* __restrict__ embedX, float* __restrict__ out)
{
    const int warp = (blockIdx.x * blockDim.x + threadIdx.x) >> 5;  // 0..16383
    const int lane = threadIdx.x & 31;
    const int b    = warp >> 8;
    const int bin  = warp & 255;

    const int* gs = g_start + b * STARTS_PER_B;
    const int  s0 = gs[bin];
    const int  s1 = gs[bin + 1];

    const int2*   sxw = g_sorted + b * S_DIM;
    const float2* ex  = reinterpret_cast<const float2*>(embedX);

    float2 acc = make_float2(0.0f, 0.0f);

    for (int base = s0; base < s1; base += 32) {
        int  idx = base + lane;
        int2 xw  = make_int2(0, 0);                 // x=0 (zero row), w=0
        if (idx < s1) xw = __ldg(&sxw[idx]);

        #pragma unroll
        for (int j = 0; j < 32; ++j) {
            int   x = __shfl_sync(0xffffffffu, xw.x, j);
            float w = __int_as_float(__shfl_sync(0xffffffffu, xw.y, j));
            float2 e = __ldg(&ex[x * 32 + lane]);
            acc.x = fmaf(w, e.x, acc.x);
            acc.y = fmaf(w, e.y, acc.y);
        }
    }

    float inv = 1.0f / ((float)(s1 - s0) + 1e-6f);
    reinterpret_cast<float2*>(out)[(b * N_BINS + bin) * 32 + lane] =
        make_float2(acc.x * inv, acc.y * inv);
}

// ---------------------------------------------------------------------------
// Inputs (metadata order):
//   d_in[0] : T        float32 [B, S]
//   d_in[1] : X_ids    int32   [B, S]
//   d_in[2] : embedX_w float32 [N_TOKENS+1, 64]
//   d_in[3] : embedW_w float32 [N_TOKENS+1, 1]
// Output    : float32 [B, 256, 64]
// ---------------------------------------------------------------------------
extern "C" void kernel_launch(void* const* d_in, const int* in_sizes, int n_in,
                              void* d_out, int out_size)
{
    const float* T      = (const float*)d_in[0];
    const int*   X_ids  = (const int*)  d_in[1];
    const float* embedX = (const float*)d_in[2];
    const float* embedW = (const float*)d_in[3];
    float*       out    = (float*)d_out;

    k_hist        <<<B_DIM * NCHUNK, 512>>>(T);
    k_scan_scatter<<<B_DIM * NCHUNK, 512>>>(X_ids, embedW);
    k_bin_reduce  <<<(B_DIM * N_BINS) / 8, 256>>>(embedX, out);
}